// round 4
// baseline (speedup 1.0000x reference)
#include <cuda_runtime.h>
#include <cstdint>
#include <cstddef>
#include <math.h>

// ---------------------------------------------------------------------------
// Problem constants
// ---------------------------------------------------------------------------
#define BB    8
#define TT    16
#define HWV   196
#define DD    768
#define NHH   12
#define HDD   64
#define HIDD  3072
#define NTOK  3136           // H*W*T
#define S1    3137           // 1 + NTOK
#define MT    25088          // B*HW*T   temporal tokens
#define MS    25216          // B*T*197  spatial tokens
#define MM    25096          // B*S1     mlp tokens

// ---------------------------------------------------------------------------
// Scratch (static device globals — no allocation allowed)
// ---------------------------------------------------------------------------
__device__ float g_ln  [(size_t)MS * DD];        // LN outputs (reused 3x)
__device__ float g_qkv [(size_t)MS * 3 * DD];    // qkv (reused 2x)
__device__ float g_att [(size_t)MS * DD];        // attention out (reused 2x)
__device__ float g_tmp [(size_t)MS * DD];        // proj outputs (reused 2x)
__device__ float g_xt2 [(size_t)MT * DD];        // xt2
__device__ float g_xnew[(size_t)MM * DD];        // x_new
__device__ float g_hid [(size_t)MM * HIDD];      // MLP hidden
__device__ float g_cls [(size_t)BB * DD];        // cls mean

// ---------------------------------------------------------------------------
// f32x2 packed-FMA helpers (sm_103a FFMA2 — PTX-only path)
// ---------------------------------------------------------------------------
__device__ __forceinline__ unsigned long long pack2(float lo, float hi) {
    unsigned long long r;
    asm("mov.b64 %0, {%1, %2};" : "=l"(r) : "f"(lo), "f"(hi));
    return r;
}
__device__ __forceinline__ void fma2(unsigned long long& d,
                                     unsigned long long a, unsigned long long b) {
    asm("fma.rn.f32x2 %0, %1, %2, %0;" : "+l"(d) : "l"(a), "l"(b));
}
__device__ __forceinline__ float2 unpack2(unsigned long long v) {
    float2 r;
    asm("mov.b64 {%0, %1}, %2;" : "=f"(r.x), "=f"(r.y) : "l"(v));
    return r;
}

// ---------------------------------------------------------------------------
// Generic tiled GEMM: C[M,N] = A[M,K] @ B[K,N] (+ epilogue)
//   EPI:     0 none, 1 +bias, 2 +bias then exact GELU
//   RESMODE: 0 none, 1 += Res[row*N+col], 2 += x-gather (temporal residual)
// BM=BN=128, BK=16, 256 threads, 8x8 per thread, FFMA2 inner product.
// N must be a multiple of 128, K a multiple of 16. M guarded.
// ---------------------------------------------------------------------------
template<int EPI, int RESMODE>
__global__ void __launch_bounds__(256, 2) gemm_kernel(
    const float* __restrict__ A, const float* __restrict__ Bw,
    const float* __restrict__ bias, const float* __restrict__ Res,
    float* __restrict__ C, int M, int N, int K)
{
    __shared__ float As[16 * 128];
    __shared__ float Bs[16 * 128];

    const int tid = threadIdx.x;
    const int bm  = blockIdx.y * 128;
    const int bn  = blockIdx.x * 128;
    const int tx  = tid & 15;
    const int ty  = tid >> 4;

    int ar[2], ak[2], bk[2], bnn[2];
#pragma unroll
    for (int l = 0; l < 2; ++l) {
        int lin = tid + l * 256;
        ar[l]  = lin >> 2;        ak[l]  = (lin & 3) << 2;
        bk[l]  = lin >> 5;        bnn[l] = (lin & 31) << 2;
    }

    float4 aR[2], bR[2];
    const int KT = K >> 4;

    auto fetch = [&](int kt) {
#pragma unroll
        for (int l = 0; l < 2; ++l) {
            int row = bm + ar[l];
            if (row < M)
                aR[l] = *reinterpret_cast<const float4*>(A + (size_t)row * K + (kt << 4) + ak[l]);
            else
                aR[l] = make_float4(0.f, 0.f, 0.f, 0.f);
            bR[l] = *reinterpret_cast<const float4*>(Bw + (size_t)((kt << 4) + bk[l]) * N + bn + bnn[l]);
        }
    };
    fetch(0);

    unsigned long long acc[8][4];
#pragma unroll
    for (int i = 0; i < 8; ++i)
#pragma unroll
        for (int j = 0; j < 4; ++j) acc[i][j] = 0ull;

    for (int kt = 0; kt < KT; ++kt) {
#pragma unroll
        for (int l = 0; l < 2; ++l) {
            As[(ak[l] + 0) * 128 + ar[l]] = aR[l].x;
            As[(ak[l] + 1) * 128 + ar[l]] = aR[l].y;
            As[(ak[l] + 2) * 128 + ar[l]] = aR[l].z;
            As[(ak[l] + 3) * 128 + ar[l]] = aR[l].w;
            *reinterpret_cast<float4*>(&Bs[bk[l] * 128 + bnn[l]]) = bR[l];
        }
        __syncthreads();
        if (kt + 1 < KT) fetch(kt + 1);

#pragma unroll
        for (int k = 0; k < 16; ++k) {
            float4 a0 = *reinterpret_cast<const float4*>(&As[k * 128 + ty * 8]);
            float4 a1 = *reinterpret_cast<const float4*>(&As[k * 128 + ty * 8 + 4]);
            const unsigned long long* bq =
                reinterpret_cast<const unsigned long long*>(&Bs[k * 128 + tx * 8]);
            unsigned long long bp0 = bq[0], bp1 = bq[1], bp2 = bq[2], bp3 = bq[3];
            unsigned long long ap[8];
            ap[0] = pack2(a0.x, a0.x); ap[1] = pack2(a0.y, a0.y);
            ap[2] = pack2(a0.z, a0.z); ap[3] = pack2(a0.w, a0.w);
            ap[4] = pack2(a1.x, a1.x); ap[5] = pack2(a1.y, a1.y);
            ap[6] = pack2(a1.z, a1.z); ap[7] = pack2(a1.w, a1.w);
#pragma unroll
            for (int i = 0; i < 8; ++i) {
                fma2(acc[i][0], ap[i], bp0);
                fma2(acc[i][1], ap[i], bp1);
                fma2(acc[i][2], ap[i], bp2);
                fma2(acc[i][3], ap[i], bp3);
            }
        }
        __syncthreads();
    }

    // epilogue
    const int col0 = bn + tx * 8;
#pragma unroll
    for (int i = 0; i < 8; ++i) {
        int row = bm + ty * 8 + i;
        if (row >= M) continue;
        float v[8];
#pragma unroll
        for (int j = 0; j < 4; ++j) {
            float2 f = unpack2(acc[i][j]);
            v[2 * j]     = f.x;
            v[2 * j + 1] = f.y;
        }
        size_t res_base = 0;
        if (RESMODE == 2) {
            int b = row / NTOK;
            res_base = ((size_t)b * S1 + 1 + (row - b * NTOK)) * (size_t)DD;
        }
#pragma unroll
        for (int j = 0; j < 8; ++j) {
            float c = v[j];
            if (EPI >= 1) c += bias[col0 + j];
            if (EPI == 2) c = 0.5f * c * (1.0f + erff(c * 0.70710678118654752f));
            if (RESMODE == 1) c += Res[(size_t)row * N + col0 + j];
            if (RESMODE == 2) c += Res[res_base + col0 + j];
            v[j] = c;
        }
        *reinterpret_cast<float4*>(C + (size_t)row * N + col0)     = make_float4(v[0], v[1], v[2], v[3]);
        *reinterpret_cast<float4*>(C + (size_t)row * N + col0 + 4) = make_float4(v[4], v[5], v[6], v[7]);
    }
}

// ---------------------------------------------------------------------------
// LayerNorm. mode 0: src0 contiguous rows. mode 1: temporal gather from x.
// mode 2: spatial gather (cls from x=src0, tokens from xt2=src1).
// grid = rows, block = 256 (768 = 3 per thread)
// ---------------------------------------------------------------------------
__global__ void ln_kernel(const float* __restrict__ src0, const float* __restrict__ src1,
                          const float* __restrict__ w, const float* __restrict__ bias,
                          float* __restrict__ out, int mode)
{
    int r = blockIdx.x;
    const float* src;
    if (mode == 0) {
        src = src0 + (size_t)r * DD;
    } else if (mode == 1) {
        int b = r / NTOK;
        src = src0 + ((size_t)b * S1 + 1 + (r - b * NTOK)) * DD;
    } else {
        int bt = r / 197, pos = r - bt * 197;
        int b = bt >> 4, t = bt & 15;
        src = (pos == 0) ? (src0 + (size_t)b * S1 * DD)
                         : (src1 + ((size_t)b * NTOK + (size_t)(pos - 1) * TT + t) * DD);
    }
    int t = threadIdx.x;
    float v0 = src[t], v1 = src[t + 256], v2 = src[t + 512];
    float s  = v0 + v1 + v2;
    float sq = v0 * v0 + v1 * v1 + v2 * v2;
#pragma unroll
    for (int off = 16; off; off >>= 1) {
        s  += __shfl_xor_sync(0xffffffffu, s, off);
        sq += __shfl_xor_sync(0xffffffffu, sq, off);
    }
    __shared__ float ss[8], sqs[8];
    __shared__ float mean_s, inv_s;
    int wid = t >> 5, lane = t & 31;
    if (lane == 0) { ss[wid] = s; sqs[wid] = sq; }
    __syncthreads();
    if (t == 0) {
        float S = 0.f, SQ = 0.f;
#pragma unroll
        for (int i = 0; i < 8; ++i) { S += ss[i]; SQ += sqs[i]; }
        float mean = S * (1.0f / 768.0f);
        float var  = SQ * (1.0f / 768.0f) - mean * mean;
        mean_s = mean;
        inv_s  = rsqrtf(var + 1e-5f);
    }
    __syncthreads();
    float mean = mean_s, inv = inv_s;
    float* o = out + (size_t)r * DD;
    o[t]       = (v0 - mean) * inv * w[t]       + bias[t];
    o[t + 256] = (v1 - mean) * inv * w[t + 256] + bias[t + 256];
    o[t + 512] = (v2 - mean) * inv * w[t + 512] + bias[t + 512];
}

// ---------------------------------------------------------------------------
// Temporal attention: 16 x 16 per (seq, head). grid (1568, 12), 256 threads.
// ---------------------------------------------------------------------------
__global__ void attn_t_kernel(const float* __restrict__ qkv, float* __restrict__ out)
{
    int seq = blockIdx.x, h = blockIdx.y;
    __shared__ float q[16][68], k[16][68], v[16][68], p[16][17];
    int tid = threadIdx.x;
    {
        int row = tid >> 4, d4 = (tid & 15) << 2;
        const float* bp = qkv + (size_t)(seq * 16 + row) * (3 * DD) + h * HDD + d4;
        *reinterpret_cast<float4*>(&q[row][d4]) = *reinterpret_cast<const float4*>(bp);
        *reinterpret_cast<float4*>(&k[row][d4]) = *reinterpret_cast<const float4*>(bp + DD);
        *reinterpret_cast<float4*>(&v[row][d4]) = *reinterpret_cast<const float4*>(bp + 2 * DD);
    }
    __syncthreads();
    int i = tid >> 4, j = tid & 15;
    float s = 0.f;
#pragma unroll
    for (int d = 0; d < 64; d += 4) {
        float4 qa = *reinterpret_cast<const float4*>(&q[i][d]);
        float4 ka = *reinterpret_cast<const float4*>(&k[j][d]);
        s += qa.x * ka.x + qa.y * ka.y + qa.z * ka.z + qa.w * ka.w;
    }
    s *= 0.125f;
    float m = s;
#pragma unroll
    for (int off = 8; off; off >>= 1) m = fmaxf(m, __shfl_xor_sync(0xffffffffu, m, off, 16));
    float e = expf(s - m);
    float sum = e;
#pragma unroll
    for (int off = 8; off; off >>= 1) sum += __shfl_xor_sync(0xffffffffu, sum, off, 16);
    p[i][j] = e / sum;
    __syncthreads();
    {
        int d = (tid & 15) << 2;
        float4 o = make_float4(0.f, 0.f, 0.f, 0.f);
#pragma unroll
        for (int jj = 0; jj < 16; ++jj) {
            float pj = p[i][jj];
            float4 vv = *reinterpret_cast<const float4*>(&v[jj][d]);
            o.x += pj * vv.x; o.y += pj * vv.y; o.z += pj * vv.z; o.w += pj * vv.w;
        }
        *reinterpret_cast<float4*>(out + (size_t)(seq * 16 + i) * DD + h * HDD + d) = o;
    }
}

// ---------------------------------------------------------------------------
// Spatial attention: 197 x 197 per (seq, head). grid (128, 12), 256 threads.
// K,V fully resident in dynamic smem; Q processed in tiles of 32.
// ---------------------------------------------------------------------------
#define SK 68     // padded row stride for K/V/Q tiles
#define SP 199    // padded row stride for P tile
#define ATTN_S_SMEM ((2 * 197 * SK + 32 * SK + 32 * SP) * (int)sizeof(float))

__global__ void attn_s_kernel(const float* __restrict__ qkv, float* __restrict__ out)
{
    extern __shared__ float sm[];
    float* Ks = sm;
    float* Vs = Ks + 197 * SK;
    float* Qs = Vs + 197 * SK;
    float* Ps = Qs + 32 * SK;

    int seq = blockIdx.x, h = blockIdx.y;
    int tid = threadIdx.x;
    size_t base = (size_t)seq * 197 * (3 * DD) + h * HDD;

    for (int idx = tid; idx < 197 * 16; idx += 256) {
        int row = idx >> 4, d4 = (idx & 15) << 2;
        const float* p = qkv + base + (size_t)row * (3 * DD) + d4;
        *reinterpret_cast<float4*>(&Ks[row * SK + d4]) = *reinterpret_cast<const float4*>(p + DD);
        *reinterpret_cast<float4*>(&Vs[row * SK + d4]) = *reinterpret_cast<const float4*>(p + 2 * DD);
    }
    __syncthreads();

    const int qi = tid >> 3;      // 0..31 (query row within tile; also softmax row; also PV row)
    const int jg = tid & 7;       // key-column phase for scores
    const int d0 = (tid & 7) * 8; // output dim group for PV

    for (int qt = 0; qt < 7; ++qt) {
        int q0 = qt * 32;
        int nq = (197 - q0 < 32) ? (197 - q0) : 32;

        for (int idx = tid; idx < nq * 16; idx += 256) {
            int row = idx >> 4, d4 = (idx & 15) << 2;
            *reinterpret_cast<float4*>(&Qs[row * SK + d4]) =
                *reinterpret_cast<const float4*>(qkv + base + (size_t)(q0 + row) * (3 * DD) + d4);
        }
        __syncthreads();

        // pass 1: raw scores into Ps (group-private row), track max
        float mx = -1e30f;
        for (int j = jg; j < 197; j += 8) {
            float s = 0.f;
#pragma unroll
            for (int d = 0; d < 64; d += 4) {
                float4 qa = *reinterpret_cast<const float4*>(&Qs[qi * SK + d]);
                float4 ka = *reinterpret_cast<const float4*>(&Ks[j * SK + d]);
                s += qa.x * ka.x + qa.y * ka.y + qa.z * ka.z + qa.w * ka.w;
            }
            s *= 0.125f;
            Ps[qi * SP + j] = s;
            mx = fmaxf(mx, s);
        }
#pragma unroll
        for (int off = 4; off; off >>= 1) mx = fmaxf(mx, __shfl_xor_sync(0xffffffffu, mx, off, 8));

        // pass 2: exp + sum (unnormalized e left in Ps)
        float sum = 0.f;
        for (int j = jg; j < 197; j += 8) {
            float e = expf(Ps[qi * SP + j] - mx);
            Ps[qi * SP + j] = e;
            sum += e;
        }
#pragma unroll
        for (int off = 4; off; off >>= 1) sum += __shfl_xor_sync(0xffffffffu, sum, off, 8);
        float inv = 1.0f / sum;
        __syncwarp();

        // PV: row qi, dims d0..d0+7
        float o[8] = {0.f, 0.f, 0.f, 0.f, 0.f, 0.f, 0.f, 0.f};
        for (int j = 0; j < 197; ++j) {
            float pj = Ps[qi * SP + j];
            float4 va = *reinterpret_cast<const float4*>(&Vs[j * SK + d0]);
            float4 vb = *reinterpret_cast<const float4*>(&Vs[j * SK + d0 + 4]);
            o[0] += pj * va.x; o[1] += pj * va.y; o[2] += pj * va.z; o[3] += pj * va.w;
            o[4] += pj * vb.x; o[5] += pj * vb.y; o[6] += pj * vb.z; o[7] += pj * vb.w;
        }
        if (qi < nq) {
            float* op = out + (size_t)(seq * 197 + q0 + qi) * DD + h * HDD + d0;
            *reinterpret_cast<float4*>(op)     = make_float4(o[0] * inv, o[1] * inv, o[2] * inv, o[3] * inv);
            *reinterpret_cast<float4*>(op + 4) = make_float4(o[4] * inv, o[5] * inv, o[6] * inv, o[7] * inv);
        }
        __syncthreads();
    }
}

// ---------------------------------------------------------------------------
// cls mean over T: grid (8, 6), block 128
// ---------------------------------------------------------------------------
__global__ void cls_mean_kernel(const float* __restrict__ rs, float* __restrict__ cls)
{
    int b = blockIdx.x;
    int col = blockIdx.y * 128 + threadIdx.x;
    float s = 0.f;
#pragma unroll
    for (int t = 0; t < 16; ++t)
        s += rs[(size_t)(b * 16 + t) * 197 * DD + col];
    cls[(size_t)b * DD + col] = s * (1.0f / 16.0f);
}

// ---------------------------------------------------------------------------
// x_new = concat(init_cls, xt2) + concat(cls_out, rs_reordered)
// ---------------------------------------------------------------------------
__global__ void build_xnew_kernel(const float* __restrict__ x, const float* __restrict__ xt2,
                                  const float* __restrict__ rs, const float* __restrict__ cls,
                                  float* __restrict__ xnew)
{
    size_t idx = (size_t)blockIdx.x * blockDim.x + threadIdx.x; // one float4
    size_t total = (size_t)BB * S1 * (DD / 4);
    if (idx >= total) return;
    size_t row = idx / (DD / 4);
    int c = (int)(idx % (DD / 4)) * 4;
    int b = (int)(row / S1);
    int pos = (int)(row % S1);
    float4 a, r;
    if (pos == 0) {
        a = *reinterpret_cast<const float4*>(x + row * DD + c);
        r = *reinterpret_cast<const float4*>(cls + (size_t)b * DD + c);
    } else {
        int n = pos - 1, hw = n >> 4, t = n & 15;
        a = *reinterpret_cast<const float4*>(xt2 + ((size_t)b * NTOK + n) * DD + c);
        r = *reinterpret_cast<const float4*>(rs + ((size_t)(b * 16 + t) * 197 + 1 + hw) * DD + c);
    }
    *reinterpret_cast<float4*>(xnew + row * DD + c) =
        make_float4(a.x + r.x, a.y + r.y, a.z + r.z, a.w + r.w);
}

// ---------------------------------------------------------------------------
// Launch
// ---------------------------------------------------------------------------
extern "C" void kernel_launch(void* const* d_in, const int* in_sizes, int n_in,
                              void* d_out, int out_size)
{
    (void)in_sizes; (void)n_in; (void)out_size;

    const float* x        = (const float*)d_in[0];
    const float* tn1_w    = (const float*)d_in[1];
    const float* tn1_b    = (const float*)d_in[2];
    const float* t_qkv_w  = (const float*)d_in[3];
    const float* t_proj_w = (const float*)d_in[4];
    const float* t_proj_b = (const float*)d_in[5];
    const float* tfc_w    = (const float*)d_in[6];
    const float* tfc_b    = (const float*)d_in[7];
    const float* n1_w     = (const float*)d_in[8];
    const float* n1_b     = (const float*)d_in[9];
    const float* s_qkv_w  = (const float*)d_in[10];
    const float* s_proj_w = (const float*)d_in[11];
    const float* s_proj_b = (const float*)d_in[12];
    const float* n2_w     = (const float*)d_in[13];
    const float* n2_b     = (const float*)d_in[14];
    const float* fc1_w    = (const float*)d_in[15];
    const float* fc1_b    = (const float*)d_in[16];
    const float* fc2_w    = (const float*)d_in[17];
    const float* fc2_b    = (const float*)d_in[18];
    float* out = (float*)d_out;

    float *ln, *qkv, *att, *tmp, *xt2, *xnew, *hid, *cls;
    cudaGetSymbolAddress((void**)&ln,   g_ln);
    cudaGetSymbolAddress((void**)&qkv,  g_qkv);
    cudaGetSymbolAddress((void**)&att,  g_att);
    cudaGetSymbolAddress((void**)&tmp,  g_tmp);
    cudaGetSymbolAddress((void**)&xt2,  g_xt2);
    cudaGetSymbolAddress((void**)&xnew, g_xnew);
    cudaGetSymbolAddress((void**)&hid,  g_hid);
    cudaGetSymbolAddress((void**)&cls,  g_cls);

    cudaFuncSetAttribute(attn_s_kernel, cudaFuncAttributeMaxDynamicSharedMemorySize, ATTN_S_SMEM);

    // ---- temporal branch ----
    ln_kernel<<<MT, 256>>>(x, nullptr, tn1_w, tn1_b, ln, 1);
    gemm_kernel<0, 0><<<dim3(18, 196), 256>>>(ln, t_qkv_w, nullptr, nullptr, qkv, MT, 3 * DD, DD);
    attn_t_kernel<<<dim3(1568, 12), 256>>>(qkv, att);
    gemm_kernel<1, 0><<<dim3(6, 196), 256>>>(att, t_proj_w, t_proj_b, nullptr, tmp, MT, DD, DD);
    gemm_kernel<1, 2><<<dim3(6, 196), 256>>>(tmp, tfc_w, tfc_b, x, xt2, MT, DD, DD); // xt2 = x[:,1:] + rt

    // ---- spatial branch ----
    ln_kernel<<<MS, 256>>>(x, xt2, n1_w, n1_b, ln, 2);
    gemm_kernel<0, 0><<<dim3(18, 197), 256>>>(ln, s_qkv_w, nullptr, nullptr, qkv, MS, 3 * DD, DD);
    attn_s_kernel<<<dim3(128, 12), 256, ATTN_S_SMEM>>>(qkv, att);
    gemm_kernel<1, 0><<<dim3(6, 197), 256>>>(att, s_proj_w, s_proj_b, nullptr, tmp, MS, DD, DD);
    cls_mean_kernel<<<dim3(8, 6), 128>>>(tmp, cls);
    build_xnew_kernel<<<(unsigned)(((size_t)BB * S1 * (DD / 4) + 255) / 256), 256>>>(x, xt2, tmp, cls, xnew);

    // ---- MLP ----
    ln_kernel<<<MM, 256>>>(xnew, nullptr, n2_w, n2_b, ln, 0);
    gemm_kernel<2, 0><<<dim3(24, 197), 256>>>(ln, fc1_w, fc1_b, nullptr, hid, MM, HIDD, DD);
    gemm_kernel<1, 1><<<dim3(6, 197), 256>>>(hid, fc2_w, fc2_b, xnew, out, MM, DD, HIDD);
}

// round 5
// speedup vs baseline: 1.0002x; 1.0002x over previous
#include <cuda_runtime.h>
#include <cstdint>
#include <cstddef>
#include <math.h>

// ---------------------------------------------------------------------------
// Problem constants
// ---------------------------------------------------------------------------
#define BB    8
#define TT    16
#define HWV   196
#define DD    768
#define NHH   12
#define HDD   64
#define HIDD  3072
#define NTOK  3136           // H*W*T
#define S1    3137           // 1 + NTOK
#define MT    25088          // B*HW*T   temporal tokens
#define MS    25216          // B*T*197  spatial tokens
#define MM    25096          // B*S1     mlp tokens

// ---------------------------------------------------------------------------
// Scratch (static device globals — no allocation allowed)
// ---------------------------------------------------------------------------
__device__ float g_ln  [(size_t)MS * DD];        // LN outputs (reused 3x)
__device__ float g_qkv [(size_t)MS * 3 * DD];    // qkv (reused 2x)
__device__ float g_att [(size_t)MS * DD];        // attention out (reused 2x)
__device__ float g_tmp [(size_t)MS * DD];        // proj outputs (reused 2x)
__device__ float g_xt2 [(size_t)MT * DD];        // xt2
__device__ float g_xnew[(size_t)MM * DD];        // x_new
__device__ float g_hid [(size_t)MM * HIDD];      // MLP hidden
__device__ float g_cls [(size_t)BB * DD];        // cls mean

// ---------------------------------------------------------------------------
// f32x2 packed-FMA helpers (sm_103a FFMA2 — PTX-only path)
// ---------------------------------------------------------------------------
__device__ __forceinline__ unsigned long long pack2(float lo, float hi) {
    unsigned long long r;
    asm("mov.b64 %0, {%1, %2};" : "=l"(r) : "f"(lo), "f"(hi));
    return r;
}
__device__ __forceinline__ void fma2(unsigned long long& d,
                                     unsigned long long a, unsigned long long b) {
    asm("fma.rn.f32x2 %0, %1, %2, %0;" : "+l"(d) : "l"(a), "l"(b));
}
__device__ __forceinline__ float2 unpack2(unsigned long long v) {
    float2 r;
    asm("mov.b64 {%0, %1}, %2;" : "=f"(r.x), "=f"(r.y) : "l"(v));
    return r;
}

// ---------------------------------------------------------------------------
// Generic tiled GEMM: C[M,N] = A[M,K] @ B[K,N] (+ epilogue)
//   EPI:     0 none, 1 +bias, 2 +bias then exact GELU
//   RESMODE: 0 none, 1 += Res[row*N+col], 2 += x-gather (temporal residual)
// BM=BN=128, BK=16, 256 threads, 8x8 per thread, FFMA2 inner product.
// N must be a multiple of 128, K a multiple of 16. M guarded.
// ---------------------------------------------------------------------------
template<int EPI, int RESMODE>
__global__ void __launch_bounds__(256, 2) gemm_kernel(
    const float* __restrict__ A, const float* __restrict__ Bw,
    const float* __restrict__ bias, const float* __restrict__ Res,
    float* __restrict__ C, int M, int N, int K)
{
    __shared__ float As[16 * 128];
    __shared__ float Bs[16 * 128];

    const int tid = threadIdx.x;
    const int bm  = blockIdx.y * 128;
    const int bn  = blockIdx.x * 128;
    const int tx  = tid & 15;
    const int ty  = tid >> 4;

    int ar[2], ak[2], bk[2], bnn[2];
#pragma unroll
    for (int l = 0; l < 2; ++l) {
        int lin = tid + l * 256;
        ar[l]  = lin >> 2;        ak[l]  = (lin & 3) << 2;
        bk[l]  = lin >> 5;        bnn[l] = (lin & 31) << 2;
    }

    float4 aR[2], bR[2];
    const int KT = K >> 4;

    auto fetch = [&](int kt) {
#pragma unroll
        for (int l = 0; l < 2; ++l) {
            int row = bm + ar[l];
            if (row < M)
                aR[l] = *reinterpret_cast<const float4*>(A + (size_t)row * K + (kt << 4) + ak[l]);
            else
                aR[l] = make_float4(0.f, 0.f, 0.f, 0.f);
            bR[l] = *reinterpret_cast<const float4*>(Bw + (size_t)((kt << 4) + bk[l]) * N + bn + bnn[l]);
        }
    };
    fetch(0);

    unsigned long long acc[8][4];
#pragma unroll
    for (int i = 0; i < 8; ++i)
#pragma unroll
        for (int j = 0; j < 4; ++j) acc[i][j] = 0ull;

    for (int kt = 0; kt < KT; ++kt) {
#pragma unroll
        for (int l = 0; l < 2; ++l) {
            As[(ak[l] + 0) * 128 + ar[l]] = aR[l].x;
            As[(ak[l] + 1) * 128 + ar[l]] = aR[l].y;
            As[(ak[l] + 2) * 128 + ar[l]] = aR[l].z;
            As[(ak[l] + 3) * 128 + ar[l]] = aR[l].w;
            *reinterpret_cast<float4*>(&Bs[bk[l] * 128 + bnn[l]]) = bR[l];
        }
        __syncthreads();
        if (kt + 1 < KT) fetch(kt + 1);

#pragma unroll
        for (int k = 0; k < 16; ++k) {
            float4 a0 = *reinterpret_cast<const float4*>(&As[k * 128 + ty * 8]);
            float4 a1 = *reinterpret_cast<const float4*>(&As[k * 128 + ty * 8 + 4]);
            const unsigned long long* bq =
                reinterpret_cast<const unsigned long long*>(&Bs[k * 128 + tx * 8]);
            unsigned long long bp0 = bq[0], bp1 = bq[1], bp2 = bq[2], bp3 = bq[3];
            unsigned long long ap[8];
            ap[0] = pack2(a0.x, a0.x); ap[1] = pack2(a0.y, a0.y);
            ap[2] = pack2(a0.z, a0.z); ap[3] = pack2(a0.w, a0.w);
            ap[4] = pack2(a1.x, a1.x); ap[5] = pack2(a1.y, a1.y);
            ap[6] = pack2(a1.z, a1.z); ap[7] = pack2(a1.w, a1.w);
#pragma unroll
            for (int i = 0; i < 8; ++i) {
                fma2(acc[i][0], ap[i], bp0);
                fma2(acc[i][1], ap[i], bp1);
                fma2(acc[i][2], ap[i], bp2);
                fma2(acc[i][3], ap[i], bp3);
            }
        }
        __syncthreads();
    }

    // epilogue
    const int col0 = bn + tx * 8;
#pragma unroll
    for (int i = 0; i < 8; ++i) {
        int row = bm + ty * 8 + i;
        if (row >= M) continue;
        float v[8];
#pragma unroll
        for (int j = 0; j < 4; ++j) {
            float2 f = unpack2(acc[i][j]);
            v[2 * j]     = f.x;
            v[2 * j + 1] = f.y;
        }
        size_t res_base = 0;
        if (RESMODE == 2) {
            int b = row / NTOK;
            res_base = ((size_t)b * S1 + 1 + (row - b * NTOK)) * (size_t)DD;
        }
#pragma unroll
        for (int j = 0; j < 8; ++j) {
            float c = v[j];
            if (EPI >= 1) c += bias[col0 + j];
            if (EPI == 2) c = 0.5f * c * (1.0f + erff(c * 0.70710678118654752f));
            if (RESMODE == 1) c += Res[(size_t)row * N + col0 + j];
            if (RESMODE == 2) c += Res[res_base + col0 + j];
            v[j] = c;
        }
        *reinterpret_cast<float4*>(C + (size_t)row * N + col0)     = make_float4(v[0], v[1], v[2], v[3]);
        *reinterpret_cast<float4*>(C + (size_t)row * N + col0 + 4) = make_float4(v[4], v[5], v[6], v[7]);
    }
}

// ---------------------------------------------------------------------------
// LayerNorm. mode 0: src0 contiguous rows. mode 1: temporal gather from x.
// mode 2: spatial gather (cls from x=src0, tokens from xt2=src1).
// grid = rows, block = 256 (768 = 3 per thread)
// ---------------------------------------------------------------------------
__global__ void ln_kernel(const float* __restrict__ src0, const float* __restrict__ src1,
                          const float* __restrict__ w, const float* __restrict__ bias,
                          float* __restrict__ out, int mode)
{
    int r = blockIdx.x;
    const float* src;
    if (mode == 0) {
        src = src0 + (size_t)r * DD;
    } else if (mode == 1) {
        int b = r / NTOK;
        src = src0 + ((size_t)b * S1 + 1 + (r - b * NTOK)) * DD;
    } else {
        int bt = r / 197, pos = r - bt * 197;
        int b = bt >> 4, t = bt & 15;
        src = (pos == 0) ? (src0 + (size_t)b * S1 * DD)
                         : (src1 + ((size_t)b * NTOK + (size_t)(pos - 1) * TT + t) * DD);
    }
    int t = threadIdx.x;
    float v0 = src[t], v1 = src[t + 256], v2 = src[t + 512];
    float s  = v0 + v1 + v2;
    float sq = v0 * v0 + v1 * v1 + v2 * v2;
#pragma unroll
    for (int off = 16; off; off >>= 1) {
        s  += __shfl_xor_sync(0xffffffffu, s, off);
        sq += __shfl_xor_sync(0xffffffffu, sq, off);
    }
    __shared__ float ss[8], sqs[8];
    __shared__ float mean_s, inv_s;
    int wid = t >> 5, lane = t & 31;
    if (lane == 0) { ss[wid] = s; sqs[wid] = sq; }
    __syncthreads();
    if (t == 0) {
        float S = 0.f, SQ = 0.f;
#pragma unroll
        for (int i = 0; i < 8; ++i) { S += ss[i]; SQ += sqs[i]; }
        float mean = S * (1.0f / 768.0f);
        float var  = SQ * (1.0f / 768.0f) - mean * mean;
        mean_s = mean;
        inv_s  = rsqrtf(var + 1e-5f);
    }
    __syncthreads();
    float mean = mean_s, inv = inv_s;
    float* o = out + (size_t)r * DD;
    o[t]       = (v0 - mean) * inv * w[t]       + bias[t];
    o[t + 256] = (v1 - mean) * inv * w[t + 256] + bias[t + 256];
    o[t + 512] = (v2 - mean) * inv * w[t + 512] + bias[t + 512];
}

// ---------------------------------------------------------------------------
// Temporal attention: 16 x 16 per (seq, head). grid (1568, 12), 256 threads.
// ---------------------------------------------------------------------------
__global__ void attn_t_kernel(const float* __restrict__ qkv, float* __restrict__ out)
{
    int seq = blockIdx.x, h = blockIdx.y;
    __shared__ float q[16][68], k[16][68], v[16][68], p[16][17];
    int tid = threadIdx.x;
    {
        int row = tid >> 4, d4 = (tid & 15) << 2;
        const float* bp = qkv + (size_t)(seq * 16 + row) * (3 * DD) + h * HDD + d4;
        *reinterpret_cast<float4*>(&q[row][d4]) = *reinterpret_cast<const float4*>(bp);
        *reinterpret_cast<float4*>(&k[row][d4]) = *reinterpret_cast<const float4*>(bp + DD);
        *reinterpret_cast<float4*>(&v[row][d4]) = *reinterpret_cast<const float4*>(bp + 2 * DD);
    }
    __syncthreads();
    int i = tid >> 4, j = tid & 15;
    float s = 0.f;
#pragma unroll
    for (int d = 0; d < 64; d += 4) {
        float4 qa = *reinterpret_cast<const float4*>(&q[i][d]);
        float4 ka = *reinterpret_cast<const float4*>(&k[j][d]);
        s += qa.x * ka.x + qa.y * ka.y + qa.z * ka.z + qa.w * ka.w;
    }
    s *= 0.125f;
    float m = s;
#pragma unroll
    for (int off = 8; off; off >>= 1) m = fmaxf(m, __shfl_xor_sync(0xffffffffu, m, off, 16));
    float e = expf(s - m);
    float sum = e;
#pragma unroll
    for (int off = 8; off; off >>= 1) sum += __shfl_xor_sync(0xffffffffu, sum, off, 16);
    p[i][j] = e / sum;
    __syncthreads();
    {
        int d = (tid & 15) << 2;
        float4 o = make_float4(0.f, 0.f, 0.f, 0.f);
#pragma unroll
        for (int jj = 0; jj < 16; ++jj) {
            float pj = p[i][jj];
            float4 vv = *reinterpret_cast<const float4*>(&v[jj][d]);
            o.x += pj * vv.x; o.y += pj * vv.y; o.z += pj * vv.z; o.w += pj * vv.w;
        }
        *reinterpret_cast<float4*>(out + (size_t)(seq * 16 + i) * DD + h * HDD + d) = o;
    }
}

// ---------------------------------------------------------------------------
// Spatial attention: 197 x 197 per (seq, head). grid (128, 12), 256 threads.
// K,V fully resident in dynamic smem; Q processed in tiles of 32.
// ---------------------------------------------------------------------------
#define SK 68     // padded row stride for K/V/Q tiles
#define SP 199    // padded row stride for P tile
#define ATTN_S_SMEM ((2 * 197 * SK + 32 * SK + 32 * SP) * (int)sizeof(float))

__global__ void attn_s_kernel(const float* __restrict__ qkv, float* __restrict__ out)
{
    extern __shared__ float sm[];
    float* Ks = sm;
    float* Vs = Ks + 197 * SK;
    float* Qs = Vs + 197 * SK;
    float* Ps = Qs + 32 * SK;

    int seq = blockIdx.x, h = blockIdx.y;
    int tid = threadIdx.x;
    size_t base = (size_t)seq * 197 * (3 * DD) + h * HDD;

    for (int idx = tid; idx < 197 * 16; idx += 256) {
        int row = idx >> 4, d4 = (idx & 15) << 2;
        const float* p = qkv + base + (size_t)row * (3 * DD) + d4;
        *reinterpret_cast<float4*>(&Ks[row * SK + d4]) = *reinterpret_cast<const float4*>(p + DD);
        *reinterpret_cast<float4*>(&Vs[row * SK + d4]) = *reinterpret_cast<const float4*>(p + 2 * DD);
    }
    __syncthreads();

    const int qi = tid >> 3;      // 0..31 (query row within tile; also softmax row; also PV row)
    const int jg = tid & 7;       // key-column phase for scores
    const int d0 = (tid & 7) * 8; // output dim group for PV

    for (int qt = 0; qt < 7; ++qt) {
        int q0 = qt * 32;
        int nq = (197 - q0 < 32) ? (197 - q0) : 32;

        for (int idx = tid; idx < nq * 16; idx += 256) {
            int row = idx >> 4, d4 = (idx & 15) << 2;
            *reinterpret_cast<float4*>(&Qs[row * SK + d4]) =
                *reinterpret_cast<const float4*>(qkv + base + (size_t)(q0 + row) * (3 * DD) + d4);
        }
        __syncthreads();

        // pass 1: raw scores into Ps (group-private row), track max
        float mx = -1e30f;
        for (int j = jg; j < 197; j += 8) {
            float s = 0.f;
#pragma unroll
            for (int d = 0; d < 64; d += 4) {
                float4 qa = *reinterpret_cast<const float4*>(&Qs[qi * SK + d]);
                float4 ka = *reinterpret_cast<const float4*>(&Ks[j * SK + d]);
                s += qa.x * ka.x + qa.y * ka.y + qa.z * ka.z + qa.w * ka.w;
            }
            s *= 0.125f;
            Ps[qi * SP + j] = s;
            mx = fmaxf(mx, s);
        }
#pragma unroll
        for (int off = 4; off; off >>= 1) mx = fmaxf(mx, __shfl_xor_sync(0xffffffffu, mx, off, 8));

        // pass 2: exp + sum (unnormalized e left in Ps)
        float sum = 0.f;
        for (int j = jg; j < 197; j += 8) {
            float e = expf(Ps[qi * SP + j] - mx);
            Ps[qi * SP + j] = e;
            sum += e;
        }
#pragma unroll
        for (int off = 4; off; off >>= 1) sum += __shfl_xor_sync(0xffffffffu, sum, off, 8);
        float inv = 1.0f / sum;
        __syncwarp();

        // PV: row qi, dims d0..d0+7
        float o[8] = {0.f, 0.f, 0.f, 0.f, 0.f, 0.f, 0.f, 0.f};
        for (int j = 0; j < 197; ++j) {
            float pj = Ps[qi * SP + j];
            float4 va = *reinterpret_cast<const float4*>(&Vs[j * SK + d0]);
            float4 vb = *reinterpret_cast<const float4*>(&Vs[j * SK + d0 + 4]);
            o[0] += pj * va.x; o[1] += pj * va.y; o[2] += pj * va.z; o[3] += pj * va.w;
            o[4] += pj * vb.x; o[5] += pj * vb.y; o[6] += pj * vb.z; o[7] += pj * vb.w;
        }
        if (qi < nq) {
            float* op = out + (size_t)(seq * 197 + q0 + qi) * DD + h * HDD + d0;
            *reinterpret_cast<float4*>(op)     = make_float4(o[0] * inv, o[1] * inv, o[2] * inv, o[3] * inv);
            *reinterpret_cast<float4*>(op + 4) = make_float4(o[4] * inv, o[5] * inv, o[6] * inv, o[7] * inv);
        }
        __syncthreads();
    }
}

// ---------------------------------------------------------------------------
// cls mean over T: grid (8, 6), block 128
// ---------------------------------------------------------------------------
__global__ void cls_mean_kernel(const float* __restrict__ rs, float* __restrict__ cls)
{
    int b = blockIdx.x;
    int col = blockIdx.y * 128 + threadIdx.x;
    float s = 0.f;
#pragma unroll
    for (int t = 0; t < 16; ++t)
        s += rs[(size_t)(b * 16 + t) * 197 * DD + col];
    cls[(size_t)b * DD + col] = s * (1.0f / 16.0f);
}

// ---------------------------------------------------------------------------
// x_new = concat(init_cls, xt2) + concat(cls_out, rs_reordered)
// ---------------------------------------------------------------------------
__global__ void build_xnew_kernel(const float* __restrict__ x, const float* __restrict__ xt2,
                                  const float* __restrict__ rs, const float* __restrict__ cls,
                                  float* __restrict__ xnew)
{
    size_t idx = (size_t)blockIdx.x * blockDim.x + threadIdx.x; // one float4
    size_t total = (size_t)BB * S1 * (DD / 4);
    if (idx >= total) return;
    size_t row = idx / (DD / 4);
    int c = (int)(idx % (DD / 4)) * 4;
    int b = (int)(row / S1);
    int pos = (int)(row % S1);
    float4 a, r;
    if (pos == 0) {
        a = *reinterpret_cast<const float4*>(x + row * DD + c);
        r = *reinterpret_cast<const float4*>(cls + (size_t)b * DD + c);
    } else {
        int n = pos - 1, hw = n >> 4, t = n & 15;
        a = *reinterpret_cast<const float4*>(xt2 + ((size_t)b * NTOK + n) * DD + c);
        r = *reinterpret_cast<const float4*>(rs + ((size_t)(b * 16 + t) * 197 + 1 + hw) * DD + c);
    }
    *reinterpret_cast<float4*>(xnew + row * DD + c) =
        make_float4(a.x + r.x, a.y + r.y, a.z + r.z, a.w + r.w);
}

// ---------------------------------------------------------------------------
// Launch
// ---------------------------------------------------------------------------
extern "C" void kernel_launch(void* const* d_in, const int* in_sizes, int n_in,
                              void* d_out, int out_size)
{
    (void)in_sizes; (void)n_in; (void)out_size;

    const float* x        = (const float*)d_in[0];
    const float* tn1_w    = (const float*)d_in[1];
    const float* tn1_b    = (const float*)d_in[2];
    const float* t_qkv_w  = (const float*)d_in[3];
    const float* t_proj_w = (const float*)d_in[4];
    const float* t_proj_b = (const float*)d_in[5];
    const float* tfc_w    = (const float*)d_in[6];
    const float* tfc_b    = (const float*)d_in[7];
    const float* n1_w     = (const float*)d_in[8];
    const float* n1_b     = (const float*)d_in[9];
    const float* s_qkv_w  = (const float*)d_in[10];
    const float* s_proj_w = (const float*)d_in[11];
    const float* s_proj_b = (const float*)d_in[12];
    const float* n2_w     = (const float*)d_in[13];
    const float* n2_b     = (const float*)d_in[14];
    const float* fc1_w    = (const float*)d_in[15];
    const float* fc1_b    = (const float*)d_in[16];
    const float* fc2_w    = (const float*)d_in[17];
    const float* fc2_b    = (const float*)d_in[18];
    float* out = (float*)d_out;

    float *ln, *qkv, *att, *tmp, *xt2, *xnew, *hid, *cls;
    cudaGetSymbolAddress((void**)&ln,   g_ln);
    cudaGetSymbolAddress((void**)&qkv,  g_qkv);
    cudaGetSymbolAddress((void**)&att,  g_att);
    cudaGetSymbolAddress((void**)&tmp,  g_tmp);
    cudaGetSymbolAddress((void**)&xt2,  g_xt2);
    cudaGetSymbolAddress((void**)&xnew, g_xnew);
    cudaGetSymbolAddress((void**)&hid,  g_hid);
    cudaGetSymbolAddress((void**)&cls,  g_cls);

    cudaFuncSetAttribute(attn_s_kernel, cudaFuncAttributeMaxDynamicSharedMemorySize, ATTN_S_SMEM);

    // ---- temporal branch ----
    ln_kernel<<<MT, 256>>>(x, nullptr, tn1_w, tn1_b, ln, 1);
    gemm_kernel<0, 0><<<dim3(18, 196), 256>>>(ln, t_qkv_w, nullptr, nullptr, qkv, MT, 3 * DD, DD);
    attn_t_kernel<<<dim3(1568, 12), 256>>>(qkv, att);
    gemm_kernel<1, 0><<<dim3(6, 196), 256>>>(att, t_proj_w, t_proj_b, nullptr, tmp, MT, DD, DD);
    gemm_kernel<1, 2><<<dim3(6, 196), 256>>>(tmp, tfc_w, tfc_b, x, xt2, MT, DD, DD); // xt2 = x[:,1:] + rt

    // ---- spatial branch ----
    ln_kernel<<<MS, 256>>>(x, xt2, n1_w, n1_b, ln, 2);
    gemm_kernel<0, 0><<<dim3(18, 197), 256>>>(ln, s_qkv_w, nullptr, nullptr, qkv, MS, 3 * DD, DD);
    attn_s_kernel<<<dim3(128, 12), 256, ATTN_S_SMEM>>>(qkv, att);
    gemm_kernel<1, 0><<<dim3(6, 197), 256>>>(att, s_proj_w, s_proj_b, nullptr, tmp, MS, DD, DD);
    cls_mean_kernel<<<dim3(8, 6), 128>>>(tmp, cls);
    build_xnew_kernel<<<(unsigned)(((size_t)BB * S1 * (DD / 4) + 255) / 256), 256>>>(x, xt2, tmp, cls, xnew);

    // ---- MLP ----
    ln_kernel<<<MM, 256>>>(xnew, nullptr, n2_w, n2_b, ln, 0);
    gemm_kernel<2, 0><<<dim3(24, 197), 256>>>(ln, fc1_w, fc1_b, nullptr, hid, MM, HIDD, DD);
    gemm_kernel<1, 1><<<dim3(6, 197), 256>>>(hid, fc2_w, fc2_b, xnew, out, MM, DD, HIDD);
}

// round 6
// speedup vs baseline: 1.0012x; 1.0010x over previous
#include <cuda_runtime.h>
#include <cstdint>
#include <cstddef>
#include <math.h>

// ---------------------------------------------------------------------------
// Problem constants
// ---------------------------------------------------------------------------
#define BB    8
#define TT    16
#define HWV   196
#define DD    768
#define NHH   12
#define HDD   64
#define HIDD  3072
#define NTOK  3136           // H*W*T
#define S1    3137           // 1 + NTOK
#define MT    25088          // B*HW*T   temporal tokens
#define MS    25216          // B*T*197  spatial tokens
#define MM    25096          // B*S1     mlp tokens

// ---------------------------------------------------------------------------
// Scratch (static device globals — no allocation allowed)
// ---------------------------------------------------------------------------
__device__ float g_ln  [(size_t)MS * DD];        // LN outputs (reused 3x)
__device__ float g_qkv [(size_t)MS * 3 * DD];    // qkv (reused 2x)
__device__ float g_att [(size_t)MS * DD];        // attention out (reused 2x)
__device__ float g_tmp [(size_t)MS * DD];        // proj outputs (reused 2x)
__device__ float g_xt2 [(size_t)MT * DD];        // xt2
__device__ float g_xnew[(size_t)MM * DD];        // x_new
__device__ float g_hid [(size_t)MM * HIDD];      // MLP hidden
__device__ float g_cls [(size_t)BB * DD];        // cls mean

// ---------------------------------------------------------------------------
// f32x2 packed-FMA helpers (sm_103a FFMA2 — PTX-only path)
// ---------------------------------------------------------------------------
__device__ __forceinline__ unsigned long long pack2(float lo, float hi) {
    unsigned long long r;
    asm("mov.b64 %0, {%1, %2};" : "=l"(r) : "f"(lo), "f"(hi));
    return r;
}
__device__ __forceinline__ void fma2(unsigned long long& d,
                                     unsigned long long a, unsigned long long b) {
    asm("fma.rn.f32x2 %0, %1, %2, %0;" : "+l"(d) : "l"(a), "l"(b));
}
__device__ __forceinline__ float2 unpack2(unsigned long long v) {
    float2 r;
    asm("mov.b64 {%0, %1}, %2;" : "=f"(r.x), "=f"(r.y) : "l"(v));
    return r;
}

// ---------------------------------------------------------------------------
// Generic tiled GEMM: C[M,N] = A[M,K] @ B[K,N] (+ epilogue)
//   EPI:     0 none, 1 +bias, 2 +bias then exact GELU
//   RESMODE: 0 none, 1 += Res[row*N+col], 2 += x-gather (temporal residual)
// BM=BN=128, BK=16, 256 threads, 8x8 per thread, FFMA2 inner product.
// N must be a multiple of 128, K a multiple of 16. M guarded.
// ---------------------------------------------------------------------------
template<int EPI, int RESMODE>
__global__ void __launch_bounds__(256, 2) gemm_kernel(
    const float* __restrict__ A, const float* __restrict__ Bw,
    const float* __restrict__ bias, const float* __restrict__ Res,
    float* __restrict__ C, int M, int N, int K)
{
    __shared__ float As[16 * 128];
    __shared__ float Bs[16 * 128];

    const int tid = threadIdx.x;
    const int bm  = blockIdx.y * 128;
    const int bn  = blockIdx.x * 128;
    const int tx  = tid & 15;
    const int ty  = tid >> 4;

    int ar[2], ak[2], bk[2], bnn[2];
#pragma unroll
    for (int l = 0; l < 2; ++l) {
        int lin = tid + l * 256;
        ar[l]  = lin >> 2;        ak[l]  = (lin & 3) << 2;
        bk[l]  = lin >> 5;        bnn[l] = (lin & 31) << 2;
    }

    float4 aR[2], bR[2];
    const int KT = K >> 4;

    auto fetch = [&](int kt) {
#pragma unroll
        for (int l = 0; l < 2; ++l) {
            int row = bm + ar[l];
            if (row < M)
                aR[l] = *reinterpret_cast<const float4*>(A + (size_t)row * K + (kt << 4) + ak[l]);
            else
                aR[l] = make_float4(0.f, 0.f, 0.f, 0.f);
            bR[l] = *reinterpret_cast<const float4*>(Bw + (size_t)((kt << 4) + bk[l]) * N + bn + bnn[l]);
        }
    };
    fetch(0);

    unsigned long long acc[8][4];
#pragma unroll
    for (int i = 0; i < 8; ++i)
#pragma unroll
        for (int j = 0; j < 4; ++j) acc[i][j] = 0ull;

    for (int kt = 0; kt < KT; ++kt) {
#pragma unroll
        for (int l = 0; l < 2; ++l) {
            As[(ak[l] + 0) * 128 + ar[l]] = aR[l].x;
            As[(ak[l] + 1) * 128 + ar[l]] = aR[l].y;
            As[(ak[l] + 2) * 128 + ar[l]] = aR[l].z;
            As[(ak[l] + 3) * 128 + ar[l]] = aR[l].w;
            *reinterpret_cast<float4*>(&Bs[bk[l] * 128 + bnn[l]]) = bR[l];
        }
        __syncthreads();
        if (kt + 1 < KT) fetch(kt + 1);

#pragma unroll
        for (int k = 0; k < 16; ++k) {
            float4 a0 = *reinterpret_cast<const float4*>(&As[k * 128 + ty * 8]);
            float4 a1 = *reinterpret_cast<const float4*>(&As[k * 128 + ty * 8 + 4]);
            const unsigned long long* bq =
                reinterpret_cast<const unsigned long long*>(&Bs[k * 128 + tx * 8]);
            unsigned long long bp0 = bq[0], bp1 = bq[1], bp2 = bq[2], bp3 = bq[3];
            unsigned long long ap[8];
            ap[0] = pack2(a0.x, a0.x); ap[1] = pack2(a0.y, a0.y);
            ap[2] = pack2(a0.z, a0.z); ap[3] = pack2(a0.w, a0.w);
            ap[4] = pack2(a1.x, a1.x); ap[5] = pack2(a1.y, a1.y);
            ap[6] = pack2(a1.z, a1.z); ap[7] = pack2(a1.w, a1.w);
#pragma unroll
            for (int i = 0; i < 8; ++i) {
                fma2(acc[i][0], ap[i], bp0);
                fma2(acc[i][1], ap[i], bp1);
                fma2(acc[i][2], ap[i], bp2);
                fma2(acc[i][3], ap[i], bp3);
            }
        }
        __syncthreads();
    }

    // epilogue
    const int col0 = bn + tx * 8;
#pragma unroll
    for (int i = 0; i < 8; ++i) {
        int row = bm + ty * 8 + i;
        if (row >= M) continue;
        float v[8];
#pragma unroll
        for (int j = 0; j < 4; ++j) {
            float2 f = unpack2(acc[i][j]);
            v[2 * j]     = f.x;
            v[2 * j + 1] = f.y;
        }
        size_t res_base = 0;
        if (RESMODE == 2) {
            int b = row / NTOK;
            res_base = ((size_t)b * S1 + 1 + (row - b * NTOK)) * (size_t)DD;
        }
#pragma unroll
        for (int j = 0; j < 8; ++j) {
            float c = v[j];
            if (EPI >= 1) c += bias[col0 + j];
            if (EPI == 2) c = 0.5f * c * (1.0f + erff(c * 0.70710678118654752f));
            if (RESMODE == 1) c += Res[(size_t)row * N + col0 + j];
            if (RESMODE == 2) c += Res[res_base + col0 + j];
            v[j] = c;
        }
        *reinterpret_cast<float4*>(C + (size_t)row * N + col0)     = make_float4(v[0], v[1], v[2], v[3]);
        *reinterpret_cast<float4*>(C + (size_t)row * N + col0 + 4) = make_float4(v[4], v[5], v[6], v[7]);
    }
}

// ---------------------------------------------------------------------------
// LayerNorm. mode 0: src0 contiguous rows. mode 1: temporal gather from x.
// mode 2: spatial gather (cls from x=src0, tokens from xt2=src1).
// grid = rows, block = 256 (768 = 3 per thread)
// ---------------------------------------------------------------------------
__global__ void ln_kernel(const float* __restrict__ src0, const float* __restrict__ src1,
                          const float* __restrict__ w, const float* __restrict__ bias,
                          float* __restrict__ out, int mode)
{
    int r = blockIdx.x;
    const float* src;
    if (mode == 0) {
        src = src0 + (size_t)r * DD;
    } else if (mode == 1) {
        int b = r / NTOK;
        src = src0 + ((size_t)b * S1 + 1 + (r - b * NTOK)) * DD;
    } else {
        int bt = r / 197, pos = r - bt * 197;
        int b = bt >> 4, t = bt & 15;
        src = (pos == 0) ? (src0 + (size_t)b * S1 * DD)
                         : (src1 + ((size_t)b * NTOK + (size_t)(pos - 1) * TT + t) * DD);
    }
    int t = threadIdx.x;
    float v0 = src[t], v1 = src[t + 256], v2 = src[t + 512];
    float s  = v0 + v1 + v2;
    float sq = v0 * v0 + v1 * v1 + v2 * v2;
#pragma unroll
    for (int off = 16; off; off >>= 1) {
        s  += __shfl_xor_sync(0xffffffffu, s, off);
        sq += __shfl_xor_sync(0xffffffffu, sq, off);
    }
    __shared__ float ss[8], sqs[8];
    __shared__ float mean_s, inv_s;
    int wid = t >> 5, lane = t & 31;
    if (lane == 0) { ss[wid] = s; sqs[wid] = sq; }
    __syncthreads();
    if (t == 0) {
        float S = 0.f, SQ = 0.f;
#pragma unroll
        for (int i = 0; i < 8; ++i) { S += ss[i]; SQ += sqs[i]; }
        float mean = S * (1.0f / 768.0f);
        float var  = SQ * (1.0f / 768.0f) - mean * mean;
        mean_s = mean;
        inv_s  = rsqrtf(var + 1e-5f);
    }
    __syncthreads();
    float mean = mean_s, inv = inv_s;
    float* o = out + (size_t)r * DD;
    o[t]       = (v0 - mean) * inv * w[t]       + bias[t];
    o[t + 256] = (v1 - mean) * inv * w[t + 256] + bias[t + 256];
    o[t + 512] = (v2 - mean) * inv * w[t + 512] + bias[t + 512];
}

// ---------------------------------------------------------------------------
// Temporal attention: 16 x 16 per (seq, head). grid (1568, 12), 256 threads.
// ---------------------------------------------------------------------------
__global__ void attn_t_kernel(const float* __restrict__ qkv, float* __restrict__ out)
{
    int seq = blockIdx.x, h = blockIdx.y;
    __shared__ float q[16][68], k[16][68], v[16][68], p[16][17];
    int tid = threadIdx.x;
    {
        int row = tid >> 4, d4 = (tid & 15) << 2;
        const float* bp = qkv + (size_t)(seq * 16 + row) * (3 * DD) + h * HDD + d4;
        *reinterpret_cast<float4*>(&q[row][d4]) = *reinterpret_cast<const float4*>(bp);
        *reinterpret_cast<float4*>(&k[row][d4]) = *reinterpret_cast<const float4*>(bp + DD);
        *reinterpret_cast<float4*>(&v[row][d4]) = *reinterpret_cast<const float4*>(bp + 2 * DD);
    }
    __syncthreads();
    int i = tid >> 4, j = tid & 15;
    float s = 0.f;
#pragma unroll
    for (int d = 0; d < 64; d += 4) {
        float4 qa = *reinterpret_cast<const float4*>(&q[i][d]);
        float4 ka = *reinterpret_cast<const float4*>(&k[j][d]);
        s += qa.x * ka.x + qa.y * ka.y + qa.z * ka.z + qa.w * ka.w;
    }
    s *= 0.125f;
    float m = s;
#pragma unroll
    for (int off = 8; off; off >>= 1) m = fmaxf(m, __shfl_xor_sync(0xffffffffu, m, off, 16));
    float e = expf(s - m);
    float sum = e;
#pragma unroll
    for (int off = 8; off; off >>= 1) sum += __shfl_xor_sync(0xffffffffu, sum, off, 16);
    p[i][j] = e / sum;
    __syncthreads();
    {
        int d = (tid & 15) << 2;
        float4 o = make_float4(0.f, 0.f, 0.f, 0.f);
#pragma unroll
        for (int jj = 0; jj < 16; ++jj) {
            float pj = p[i][jj];
            float4 vv = *reinterpret_cast<const float4*>(&v[jj][d]);
            o.x += pj * vv.x; o.y += pj * vv.y; o.z += pj * vv.z; o.w += pj * vv.w;
        }
        *reinterpret_cast<float4*>(out + (size_t)(seq * 16 + i) * DD + h * HDD + d) = o;
    }
}

// ---------------------------------------------------------------------------
// Spatial attention: 197 x 197 per (seq, head). grid (128, 12), 256 threads.
// K,V fully resident in dynamic smem; Q processed in tiles of 32.
// ---------------------------------------------------------------------------
#define SK 68     // padded row stride for K/V/Q tiles
#define SP 199    // padded row stride for P tile
#define ATTN_S_SMEM ((2 * 197 * SK + 32 * SK + 32 * SP) * (int)sizeof(float))

__global__ void attn_s_kernel(const float* __restrict__ qkv, float* __restrict__ out)
{
    extern __shared__ float sm[];
    float* Ks = sm;
    float* Vs = Ks + 197 * SK;
    float* Qs = Vs + 197 * SK;
    float* Ps = Qs + 32 * SK;

    int seq = blockIdx.x, h = blockIdx.y;
    int tid = threadIdx.x;
    size_t base = (size_t)seq * 197 * (3 * DD) + h * HDD;

    for (int idx = tid; idx < 197 * 16; idx += 256) {
        int row = idx >> 4, d4 = (idx & 15) << 2;
        const float* p = qkv + base + (size_t)row * (3 * DD) + d4;
        *reinterpret_cast<float4*>(&Ks[row * SK + d4]) = *reinterpret_cast<const float4*>(p + DD);
        *reinterpret_cast<float4*>(&Vs[row * SK + d4]) = *reinterpret_cast<const float4*>(p + 2 * DD);
    }
    __syncthreads();

    const int qi = tid >> 3;      // 0..31 (query row within tile; also softmax row; also PV row)
    const int jg = tid & 7;       // key-column phase for scores
    const int d0 = (tid & 7) * 8; // output dim group for PV

    for (int qt = 0; qt < 7; ++qt) {
        int q0 = qt * 32;
        int nq = (197 - q0 < 32) ? (197 - q0) : 32;

        for (int idx = tid; idx < nq * 16; idx += 256) {
            int row = idx >> 4, d4 = (idx & 15) << 2;
            *reinterpret_cast<float4*>(&Qs[row * SK + d4]) =
                *reinterpret_cast<const float4*>(qkv + base + (size_t)(q0 + row) * (3 * DD) + d4);
        }
        __syncthreads();

        // pass 1: raw scores into Ps (group-private row), track max
        float mx = -1e30f;
        for (int j = jg; j < 197; j += 8) {
            float s = 0.f;
#pragma unroll
            for (int d = 0; d < 64; d += 4) {
                float4 qa = *reinterpret_cast<const float4*>(&Qs[qi * SK + d]);
                float4 ka = *reinterpret_cast<const float4*>(&Ks[j * SK + d]);
                s += qa.x * ka.x + qa.y * ka.y + qa.z * ka.z + qa.w * ka.w;
            }
            s *= 0.125f;
            Ps[qi * SP + j] = s;
            mx = fmaxf(mx, s);
        }
#pragma unroll
        for (int off = 4; off; off >>= 1) mx = fmaxf(mx, __shfl_xor_sync(0xffffffffu, mx, off, 8));

        // pass 2: exp + sum (unnormalized e left in Ps)
        float sum = 0.f;
        for (int j = jg; j < 197; j += 8) {
            float e = expf(Ps[qi * SP + j] - mx);
            Ps[qi * SP + j] = e;
            sum += e;
        }
#pragma unroll
        for (int off = 4; off; off >>= 1) sum += __shfl_xor_sync(0xffffffffu, sum, off, 8);
        float inv = 1.0f / sum;
        __syncwarp();

        // PV: row qi, dims d0..d0+7
        float o[8] = {0.f, 0.f, 0.f, 0.f, 0.f, 0.f, 0.f, 0.f};
        for (int j = 0; j < 197; ++j) {
            float pj = Ps[qi * SP + j];
            float4 va = *reinterpret_cast<const float4*>(&Vs[j * SK + d0]);
            float4 vb = *reinterpret_cast<const float4*>(&Vs[j * SK + d0 + 4]);
            o[0] += pj * va.x; o[1] += pj * va.y; o[2] += pj * va.z; o[3] += pj * va.w;
            o[4] += pj * vb.x; o[5] += pj * vb.y; o[6] += pj * vb.z; o[7] += pj * vb.w;
        }
        if (qi < nq) {
            float* op = out + (size_t)(seq * 197 + q0 + qi) * DD + h * HDD + d0;
            *reinterpret_cast<float4*>(op)     = make_float4(o[0] * inv, o[1] * inv, o[2] * inv, o[3] * inv);
            *reinterpret_cast<float4*>(op + 4) = make_float4(o[4] * inv, o[5] * inv, o[6] * inv, o[7] * inv);
        }
        __syncthreads();
    }
}

// ---------------------------------------------------------------------------
// cls mean over T: grid (8, 6), block 128
// ---------------------------------------------------------------------------
__global__ void cls_mean_kernel(const float* __restrict__ rs, float* __restrict__ cls)
{
    int b = blockIdx.x;
    int col = blockIdx.y * 128 + threadIdx.x;
    float s = 0.f;
#pragma unroll
    for (int t = 0; t < 16; ++t)
        s += rs[(size_t)(b * 16 + t) * 197 * DD + col];
    cls[(size_t)b * DD + col] = s * (1.0f / 16.0f);
}

// ---------------------------------------------------------------------------
// x_new = concat(init_cls, xt2) + concat(cls_out, rs_reordered)
// ---------------------------------------------------------------------------
__global__ void build_xnew_kernel(const float* __restrict__ x, const float* __restrict__ xt2,
                                  const float* __restrict__ rs, const float* __restrict__ cls,
                                  float* __restrict__ xnew)
{
    size_t idx = (size_t)blockIdx.x * blockDim.x + threadIdx.x; // one float4
    size_t total = (size_t)BB * S1 * (DD / 4);
    if (idx >= total) return;
    size_t row = idx / (DD / 4);
    int c = (int)(idx % (DD / 4)) * 4;
    int b = (int)(row / S1);
    int pos = (int)(row % S1);
    float4 a, r;
    if (pos == 0) {
        a = *reinterpret_cast<const float4*>(x + row * DD + c);
        r = *reinterpret_cast<const float4*>(cls + (size_t)b * DD + c);
    } else {
        int n = pos - 1, hw = n >> 4, t = n & 15;
        a = *reinterpret_cast<const float4*>(xt2 + ((size_t)b * NTOK + n) * DD + c);
        r = *reinterpret_cast<const float4*>(rs + ((size_t)(b * 16 + t) * 197 + 1 + hw) * DD + c);
    }
    *reinterpret_cast<float4*>(xnew + row * DD + c) =
        make_float4(a.x + r.x, a.y + r.y, a.z + r.z, a.w + r.w);
}

// ---------------------------------------------------------------------------
// Launch
// ---------------------------------------------------------------------------
extern "C" void kernel_launch(void* const* d_in, const int* in_sizes, int n_in,
                              void* d_out, int out_size)
{
    (void)in_sizes; (void)n_in; (void)out_size;

    const float* x        = (const float*)d_in[0];
    const float* tn1_w    = (const float*)d_in[1];
    const float* tn1_b    = (const float*)d_in[2];
    const float* t_qkv_w  = (const float*)d_in[3];
    const float* t_proj_w = (const float*)d_in[4];
    const float* t_proj_b = (const float*)d_in[5];
    const float* tfc_w    = (const float*)d_in[6];
    const float* tfc_b    = (const float*)d_in[7];
    const float* n1_w     = (const float*)d_in[8];
    const float* n1_b     = (const float*)d_in[9];
    const float* s_qkv_w  = (const float*)d_in[10];
    const float* s_proj_w = (const float*)d_in[11];
    const float* s_proj_b = (const float*)d_in[12];
    const float* n2_w     = (const float*)d_in[13];
    const float* n2_b     = (const float*)d_in[14];
    const float* fc1_w    = (const float*)d_in[15];
    const float* fc1_b    = (const float*)d_in[16];
    const float* fc2_w    = (const float*)d_in[17];
    const float* fc2_b    = (const float*)d_in[18];
    float* out = (float*)d_out;

    float *ln, *qkv, *att, *tmp, *xt2, *xnew, *hid, *cls;
    cudaGetSymbolAddress((void**)&ln,   g_ln);
    cudaGetSymbolAddress((void**)&qkv,  g_qkv);
    cudaGetSymbolAddress((void**)&att,  g_att);
    cudaGetSymbolAddress((void**)&tmp,  g_tmp);
    cudaGetSymbolAddress((void**)&xt2,  g_xt2);
    cudaGetSymbolAddress((void**)&xnew, g_xnew);
    cudaGetSymbolAddress((void**)&hid,  g_hid);
    cudaGetSymbolAddress((void**)&cls,  g_cls);

    cudaFuncSetAttribute(attn_s_kernel, cudaFuncAttributeMaxDynamicSharedMemorySize, ATTN_S_SMEM);

    // ---- temporal branch ----
    ln_kernel<<<MT, 256>>>(x, nullptr, tn1_w, tn1_b, ln, 1);
    gemm_kernel<0, 0><<<dim3(18, 196), 256>>>(ln, t_qkv_w, nullptr, nullptr, qkv, MT, 3 * DD, DD);
    attn_t_kernel<<<dim3(1568, 12), 256>>>(qkv, att);
    gemm_kernel<1, 0><<<dim3(6, 196), 256>>>(att, t_proj_w, t_proj_b, nullptr, tmp, MT, DD, DD);
    gemm_kernel<1, 2><<<dim3(6, 196), 256>>>(tmp, tfc_w, tfc_b, x, xt2, MT, DD, DD); // xt2 = x[:,1:] + rt

    // ---- spatial branch ----
    ln_kernel<<<MS, 256>>>(x, xt2, n1_w, n1_b, ln, 2);
    gemm_kernel<0, 0><<<dim3(18, 197), 256>>>(ln, s_qkv_w, nullptr, nullptr, qkv, MS, 3 * DD, DD);
    attn_s_kernel<<<dim3(128, 12), 256, ATTN_S_SMEM>>>(qkv, att);
    gemm_kernel<1, 0><<<dim3(6, 197), 256>>>(att, s_proj_w, s_proj_b, nullptr, tmp, MS, DD, DD);
    cls_mean_kernel<<<dim3(8, 6), 128>>>(tmp, cls);
    build_xnew_kernel<<<(unsigned)(((size_t)BB * S1 * (DD / 4) + 255) / 256), 256>>>(x, xt2, tmp, cls, xnew);

    // ---- MLP ----
    ln_kernel<<<MM, 256>>>(xnew, nullptr, n2_w, n2_b, ln, 0);
    gemm_kernel<2, 0><<<dim3(24, 197), 256>>>(ln, fc1_w, fc1_b, nullptr, hid, MM, HIDD, DD);
    gemm_kernel<1, 1><<<dim3(6, 197), 256>>>(hid, fc2_w, fc2_b, xnew, out, MM, DD, HIDD);
}